// round 12
// baseline (speedup 1.0000x reference)
#include <cuda_runtime.h>
#include <cstdint>

// DeltaSynapse: I[b,o] = sum_e Weff[b,e,o] * sum_d (Xd[d,b,e]*(Wshort[d,b,e]+1)) * delaymap[d,e,o]
// Weff[b,e,o] = sg[e,o]*(W[e,o]*(1-frac[e,o]) + Wlong[b,e,o]*frac[e,o])
//
// D=8, B=16, N=2048. HBM-bound (~417 MB unique).
// R7 (WIN 79.9): 148 CTAs (1/SM), 512 thr, float2/thread, 26 streams x 4KB runs.
// R8/R9 (neutral/fail): DRAM pinned ~70% across tiles/waves/prefetch.
// R10: discriminating experiment — Wlong (16 streams, 70% of bytes) moves to a
// cp.async.bulk 2-stage SMEM pipeline, fetched one e-iter ahead with zero
// register/scoreboard cost. Stream geometry identical to R7 (unlike R6's
// 1024-CTA/1KB-slice confound). Tests "demand-burst HBM idle" vs "chip ceiling".

#define NN 2048
#define BB 16
#define DD 8
#define EC_MAX 28      // 74 chunks x 28 >= 2048
#define THREADS 512
#define OTILE 1024
#define STAGES 2
#define WL_SLICE_B (OTILE * 4)            // 4096 B per Wlong stream slice
#define WL_STAGE_B (BB * WL_SLICE_B)      // 64 KB per stage
#define COEF_ELEMS (EC_MAX * DD * BB)
#define SMEM_BYTES (STAGES * WL_STAGE_B + COEF_ELEMS * 4 + EC_MAX * 4 + 2 * STAGES * 8 + 16)

__device__ __forceinline__ uint32_t s2u(const void* p) {
    uint32_t a;
    asm("{ .reg .u64 t; cvta.to.shared.u64 t, %1; cvt.u32.u64 %0, t; }"
        : "=r"(a) : "l"(p));
    return a;
}
__device__ __forceinline__ void mbar_init(uint32_t a, uint32_t cnt) {
    asm volatile("mbarrier.init.shared.b64 [%0], %1;" :: "r"(a), "r"(cnt) : "memory");
}
__device__ __forceinline__ void mbar_expect_tx(uint32_t a, uint32_t bytes) {
    asm volatile("mbarrier.arrive.expect_tx.shared.b64 _, [%0], %1;"
                 :: "r"(a), "r"(bytes) : "memory");
}
__device__ __forceinline__ void mbar_arrive(uint32_t a) {
    asm volatile("mbarrier.arrive.shared.b64 _, [%0];" :: "r"(a) : "memory");
}
__device__ __forceinline__ void mbar_wait(uint32_t a, uint32_t parity) {
    asm volatile(
        "{\n\t.reg .pred P;\n"
        "WL_%=:\n\t"
        "mbarrier.try_wait.parity.acquire.cta.shared::cta.b64 P, [%0], %1, 0x989680;\n\t"
        "@P bra WD_%=;\n\t"
        "bra WL_%=;\n"
        "WD_%=:\n\t}"
        :: "r"(a), "r"(parity) : "memory");
}
__device__ __forceinline__ void bulk_g2s(uint32_t dst, const void* src,
                                         uint32_t bytes, uint32_t mbar) {
    asm volatile(
        "cp.async.bulk.shared::cta.global.mbarrier::complete_tx::bytes [%0], [%1], %2, [%3];"
        :: "r"(dst), "l"(src), "r"(bytes), "r"(mbar) : "memory");
}

__global__ void ds_zero_kernel(float* __restrict__ out, int n) {
    int i = blockIdx.x * blockDim.x + threadIdx.x;
    if (i < n) out[i] = 0.0f;
}

__global__ __launch_bounds__(THREADS, 1) void ds_main_kernel(
    const float* __restrict__ W,         // (N,N)
    const float* __restrict__ Wlong,     // (B,N,N)
    const float* __restrict__ Wshort,    // (D,B,N)
    const float* __restrict__ Xd,        // (D,B,N)
    const float* __restrict__ delaymap,  // (D,N,N)
    const float* __restrict__ frac,      // (N,N)
    const float* __restrict__ signs_pre, // (N,)
    float* __restrict__ out)             // (B,N)
{
    extern __shared__ char smem[];
    float*    wlbuf  = (float*)smem;                          // [STAGES][BB][OTILE]
    float*    coef   = (float*)(smem + STAGES * WL_STAGE_B);  // [el][d][b]
    float*    sgn_sh = coef + COEF_ELEMS;
    uint64_t* bars   = (uint64_t*)(sgn_sh + EC_MAX);

    const int tid  = threadIdx.x;
    const int o0   = blockIdx.x * OTILE;
    const int o    = o0 + tid * 2;
    const int e0   = blockIdx.y * EC_MAX;
    const int eend = min(e0 + EC_MAX, NN);
    const int ecnt = eend - e0;

    const uint32_t buf_u32  = s2u(wlbuf);
    const uint32_t bars_u32 = s2u(bars);
#define FULL_BAR(s)  (bars_u32 + (uint32_t)(s) * 8)
#define EMPTY_BAR(s) (bars_u32 + (uint32_t)(STAGES + (s)) * 8)

    if (tid == 0) {
#pragma unroll
        for (int s = 0; s < STAGES; s++) {
            mbar_init(FULL_BAR(s), 1);
            mbar_init(EMPTY_BAR(s), THREADS);
        }
    }
    __syncthreads();

    // Kick the Wlong pipeline: prefetch first min(STAGES, ecnt) e-slices.
    if (tid == 0) {
#pragma unroll
        for (int s = 0; s < STAGES; s++) {
            if (s < ecnt) {
                const long beo = (long)(e0 + s) * NN + o0;
                uint32_t dst = buf_u32 + (uint32_t)s * WL_STAGE_B;
                mbar_expect_tx(FULL_BAR(s), WL_STAGE_B);
#pragma unroll
                for (int b = 0; b < BB; b++)
                    bulk_g2s(dst + b * WL_SLICE_B,
                             Wlong + (long)b * NN * NN + beo,
                             WL_SLICE_B, FULL_BAR(s));
            }
        }
    }

    // Coef preload (overlaps TMA prologue; coalesced in e).
    for (int idx = tid; idx < DD * BB * EC_MAX; idx += THREADS) {
        int el   = idx % EC_MAX;
        int rest = idx / EC_MAX;
        int b    = rest % BB;
        int d    = rest / BB;
        if (el < ecnt) {
            int gi = (d * BB + b) * NN + (e0 + el);
            coef[(el * DD + d) * BB + b] = Xd[gi] * (Wshort[gi] + 1.0f);
        }
    }
    if (tid < ecnt) {
        float sp = signs_pre[e0 + tid];
        sgn_sh[tid] = (sp > 0.0f) ? 1.0f : ((sp < 0.0f) ? -1.0f : 0.0f);
    }
    __syncthreads();

    float2 acc[BB];
#pragma unroll
    for (int b = 0; b < BB; b++) acc[b] = make_float2(0.f, 0.f);

    for (int el = 0; el < ecnt; el++) {
        const int e = e0 + el;
        const long base_eo = (long)e * NN + o;
        const int s = el % STAGES;
        const uint32_t ph = (uint32_t)(el / STAGES) & 1u;

        // Demand streams (10 of 26) — scalar float2, evict-first.
        const float2 w2 = __ldcs((const float2*)(W + base_eo));
        const float2 f2 = __ldcs((const float2*)(frac + base_eo));
        const float se = sgn_sh[el];

        const float sgx = (w2.x > 0.0f) ? se : 0.0f;
        const float sgy = (w2.y > 0.0f) ? se : 0.0f;
        float2 cbase, fs;
        cbase.x = sgx * w2.x * (1.0f - f2.x);  fs.x = sgx * f2.x;
        cbase.y = sgy * w2.y * (1.0f - f2.y);  fs.y = sgy * f2.y;

        float2 dm[DD];
#pragma unroll
        for (int d = 0; d < DD; d++)
            dm[d] = __ldcs((const float2*)(delaymap + (long)d * NN * NN + base_eo));

        // Wlong arrives via TMA into smem (fetched one e-iter ahead).
        mbar_wait(FULL_BAR(s), ph);
        const float* st = wlbuf + s * (BB * OTILE);
        const float4* cel = (const float4*)(coef + el * DD * BB);

#pragma unroll
        for (int g = 0; g < BB / 4; g++) {
            float2 p0 = make_float2(0.f, 0.f), p1 = p0, p2 = p0, p3 = p0;
#pragma unroll
            for (int d = 0; d < DD; d++) {
                const float4 c = cel[d * (BB / 4) + g];   // LDS.128 broadcast
                p0.x = fmaf(dm[d].x, c.x, p0.x);  p0.y = fmaf(dm[d].y, c.x, p0.y);
                p1.x = fmaf(dm[d].x, c.y, p1.x);  p1.y = fmaf(dm[d].y, c.y, p1.y);
                p2.x = fmaf(dm[d].x, c.z, p2.x);  p2.y = fmaf(dm[d].y, c.z, p2.y);
                p3.x = fmaf(dm[d].x, c.w, p3.x);  p3.y = fmaf(dm[d].y, c.w, p3.y);
            }
            const int b0 = 4 * g;
            const float2 wl0 = *(const float2*)(st + (b0 + 0) * OTILE + tid * 2);
            const float2 wl1 = *(const float2*)(st + (b0 + 1) * OTILE + tid * 2);
            const float2 wl2 = *(const float2*)(st + (b0 + 2) * OTILE + tid * 2);
            const float2 wl3 = *(const float2*)(st + (b0 + 3) * OTILE + tid * 2);

            acc[b0 + 0].x = fmaf(fmaf(fs.x, wl0.x, cbase.x), p0.x, acc[b0 + 0].x);
            acc[b0 + 0].y = fmaf(fmaf(fs.y, wl0.y, cbase.y), p0.y, acc[b0 + 0].y);
            acc[b0 + 1].x = fmaf(fmaf(fs.x, wl1.x, cbase.x), p1.x, acc[b0 + 1].x);
            acc[b0 + 1].y = fmaf(fmaf(fs.y, wl1.y, cbase.y), p1.y, acc[b0 + 1].y);
            acc[b0 + 2].x = fmaf(fmaf(fs.x, wl2.x, cbase.x), p2.x, acc[b0 + 2].x);
            acc[b0 + 2].y = fmaf(fmaf(fs.y, wl2.y, cbase.y), p2.y, acc[b0 + 2].y);
            acc[b0 + 3].x = fmaf(fmaf(fs.x, wl3.x, cbase.x), p3.x, acc[b0 + 3].x);
            acc[b0 + 3].y = fmaf(fmaf(fs.y, wl3.y, cbase.y), p3.y, acc[b0 + 3].y);
        }

        mbar_arrive(EMPTY_BAR(s));  // done reading stage s

        const int nel = el + STAGES;
        if (nel < ecnt && tid == 0) {
            mbar_wait(EMPTY_BAR(s), ph);  // all 512 consumed -> reuse slot
            const long beo = (long)(e0 + nel) * NN + o0;
            uint32_t dst = buf_u32 + (uint32_t)s * WL_STAGE_B;
            mbar_expect_tx(FULL_BAR(s), WL_STAGE_B);
#pragma unroll
            for (int b = 0; b < BB; b++)
                bulk_g2s(dst + b * WL_SLICE_B,
                         Wlong + (long)b * NN * NN + beo,
                         WL_SLICE_B, FULL_BAR(s));
        }
    }

#pragma unroll
    for (int b = 0; b < BB; b++) {
        atomicAdd(&out[b * NN + o + 0], acc[b].x);
        atomicAdd(&out[b * NN + o + 1], acc[b].y);
    }
}

extern "C" void kernel_launch(void* const* d_in, const int* in_sizes, int n_in,
                              void* d_out, int out_size) {
    const float* W         = (const float*)d_in[0];
    const float* Wlong     = (const float*)d_in[1];
    const float* Wshort    = (const float*)d_in[2];
    const float* Xd        = (const float*)d_in[3];
    const float* delaymap  = (const float*)d_in[4];
    const float* STDP_frac = (const float*)d_in[5];
    const float* signs_pre = (const float*)d_in[6];
    float* out = (float*)d_out;

    cudaFuncSetAttribute(ds_main_kernel,
                         cudaFuncAttributeMaxDynamicSharedMemorySize, SMEM_BYTES);

    ds_zero_kernel<<<(BB * NN + 255) / 256, 256>>>(out, BB * NN);

    dim3 grid(NN / OTILE, (NN + EC_MAX - 1) / EC_MAX); // (2, 74) = 148 CTAs
    ds_main_kernel<<<grid, THREADS, SMEM_BYTES>>>(W, Wlong, Wshort, Xd, delaymap,
                                                  STDP_frac, signs_pre, out);
}

// round 15
// speedup vs baseline: 1.1158x; 1.1158x over previous
#include <cuda_runtime.h>

// DeltaSynapse: I[b,o] = sum_e Weff[b,e,o] * sum_d (Xd[d,b,e]*(Wshort[d,b,e]+1)) * delaymap[d,e,o]
// Weff[b,e,o] = sg[e,o]*(W[e,o]*(1-frac[e,o]) + Wlong[b,e,o]*frac[e,o])
//
// D=8, B=16, N=2048. HBM-bound: 417 MB unique, measured ceiling so far
// 5.65 TB/s (R7/R8 at the floor it implies). R12 design (infra-failed twice,
// resubmitted unchanged): full-row streams — OTILE=2048 (float4/thread), so
// each stream reads 14 adjacent 8KB rows = 112KB fully contiguous per chunk
// (max run length; R1->R7 trend says run length is the BW lever). b split
// 8/8 across paired CTAs to keep acc at 32 regs (R4 lesson). Shared streams
// (W/frac/delaymap) read by both CTAs of a pair -> __ldg (L2 reuse);
// Wlong read-once -> __ldcs.

#define NN 2048
#define BB 16
#define DD 8
#define BH 8           // batches per CTA (b-half)
#define EC_MAX 14
#define THREADS 512
#define OTILE 2048

__global__ void ds_zero_kernel(float* __restrict__ out, int n) {
    int i = blockIdx.x * blockDim.x + threadIdx.x;
    if (i < n) out[i] = 0.0f;
}

__global__ __launch_bounds__(THREADS, 1) void ds_main_kernel(
    const float* __restrict__ W,         // (N,N)
    const float* __restrict__ Wlong,     // (B,N,N)
    const float* __restrict__ Wshort,    // (D,B,N)
    const float* __restrict__ Xd,        // (D,B,N)
    const float* __restrict__ delaymap,  // (D,N,N)
    const float* __restrict__ frac,      // (N,N)
    const float* __restrict__ signs_pre, // (N,)
    float* __restrict__ out)             // (B,N)
{
    __shared__ __align__(16) float coef[EC_MAX][DD][BH]; // b fastest -> LDS.128
    __shared__ float sgn_sh[EC_MAX];

    const int tid  = threadIdx.x;
    const int o    = tid * 4;                  // full row: o in [0,2048)
    const int bh   = blockIdx.x;               // 0/1 -> batches bh*8..bh*8+7
    const int e0   = blockIdx.y * EC_MAX;
    const int eend = min(e0 + EC_MAX, NN);
    const int ecnt = eend - e0;

    // Cooperative coef preload (coalesced in e).
    for (int idx = tid; idx < DD * BH * EC_MAX; idx += THREADS) {
        int el   = idx % EC_MAX;
        int rest = idx / EC_MAX;
        int bl   = rest % BH;
        int d    = rest / BH;
        if (el < ecnt) {
            int bglob = bh * BH + bl;
            int gi = (d * BB + bglob) * NN + (e0 + el);
            coef[el][d][bl] = Xd[gi] * (Wshort[gi] + 1.0f);
        }
    }
    if (tid < ecnt) {
        float sp = signs_pre[e0 + tid];
        sgn_sh[tid] = (sp > 0.0f) ? 1.0f : ((sp < 0.0f) ? -1.0f : 0.0f);
    }
    __syncthreads();

    float4 acc[BH];
#pragma unroll
    for (int j = 0; j < BH; j++) acc[j] = make_float4(0.f, 0.f, 0.f, 0.f);

    for (int el = 0; el < ecnt; el++) {
        const int e = e0 + el;
        const long base_eo = (long)e * NN + o;

        const float4 w4 = __ldg((const float4*)(W + base_eo));
        const float4 f4 = __ldg((const float4*)(frac + base_eo));
        const float se  = sgn_sh[el];

        float4 cbase, fs;
        {
            const float sgx = (w4.x > 0.0f) ? se : 0.0f;
            const float sgy = (w4.y > 0.0f) ? se : 0.0f;
            const float sgz = (w4.z > 0.0f) ? se : 0.0f;
            const float sgw = (w4.w > 0.0f) ? se : 0.0f;
            cbase.x = sgx * w4.x * (1.0f - f4.x);  fs.x = sgx * f4.x;
            cbase.y = sgy * w4.y * (1.0f - f4.y);  fs.y = sgy * f4.y;
            cbase.z = sgz * w4.z * (1.0f - f4.z);  fs.z = sgz * f4.z;
            cbase.w = sgw * w4.w * (1.0f - f4.w);  fs.w = sgw * f4.w;
        }

        float4 dm[DD];
#pragma unroll
        for (int d = 0; d < DD; d++)
            dm[d] = __ldg((const float4*)(delaymap + (long)d * NN * NN + base_eo));

#pragma unroll
        for (int g = 0; g < BH / 4; g++) {   // two groups of 4 batches
            const int bg0 = bh * BH + g * 4; // global batch base
            const float4 wl0 = __ldcs((const float4*)(Wlong + (long)(bg0 + 0) * NN * NN + base_eo));
            const float4 wl1 = __ldcs((const float4*)(Wlong + (long)(bg0 + 1) * NN * NN + base_eo));
            const float4 wl2 = __ldcs((const float4*)(Wlong + (long)(bg0 + 2) * NN * NN + base_eo));
            const float4 wl3 = __ldcs((const float4*)(Wlong + (long)(bg0 + 3) * NN * NN + base_eo));

            float4 p0 = make_float4(0.f, 0.f, 0.f, 0.f), p1 = p0, p2 = p0, p3 = p0;
#pragma unroll
            for (int d = 0; d < DD; d++) {
                const float4 c = *(const float4*)&coef[el][d][g * 4]; // LDS.128 bcast
                p0.x = fmaf(dm[d].x, c.x, p0.x);  p0.y = fmaf(dm[d].y, c.x, p0.y);
                p0.z = fmaf(dm[d].z, c.x, p0.z);  p0.w = fmaf(dm[d].w, c.x, p0.w);
                p1.x = fmaf(dm[d].x, c.y, p1.x);  p1.y = fmaf(dm[d].y, c.y, p1.y);
                p1.z = fmaf(dm[d].z, c.y, p1.z);  p1.w = fmaf(dm[d].w, c.y, p1.w);
                p2.x = fmaf(dm[d].x, c.z, p2.x);  p2.y = fmaf(dm[d].y, c.z, p2.y);
                p2.z = fmaf(dm[d].z, c.z, p2.z);  p2.w = fmaf(dm[d].w, c.z, p2.w);
                p3.x = fmaf(dm[d].x, c.w, p3.x);  p3.y = fmaf(dm[d].y, c.w, p3.y);
                p3.z = fmaf(dm[d].z, c.w, p3.z);  p3.w = fmaf(dm[d].w, c.w, p3.w);
            }

            const int a0 = g * 4;
            acc[a0 + 0].x = fmaf(fmaf(fs.x, wl0.x, cbase.x), p0.x, acc[a0 + 0].x);
            acc[a0 + 0].y = fmaf(fmaf(fs.y, wl0.y, cbase.y), p0.y, acc[a0 + 0].y);
            acc[a0 + 0].z = fmaf(fmaf(fs.z, wl0.z, cbase.z), p0.z, acc[a0 + 0].z);
            acc[a0 + 0].w = fmaf(fmaf(fs.w, wl0.w, cbase.w), p0.w, acc[a0 + 0].w);
            acc[a0 + 1].x = fmaf(fmaf(fs.x, wl1.x, cbase.x), p1.x, acc[a0 + 1].x);
            acc[a0 + 1].y = fmaf(fmaf(fs.y, wl1.y, cbase.y), p1.y, acc[a0 + 1].y);
            acc[a0 + 1].z = fmaf(fmaf(fs.z, wl1.z, cbase.z), p1.z, acc[a0 + 1].z);
            acc[a0 + 1].w = fmaf(fmaf(fs.w, wl1.w, cbase.w), p1.w, acc[a0 + 1].w);
            acc[a0 + 2].x = fmaf(fmaf(fs.x, wl2.x, cbase.x), p2.x, acc[a0 + 2].x);
            acc[a0 + 2].y = fmaf(fmaf(fs.y, wl2.y, cbase.y), p2.y, acc[a0 + 2].y);
            acc[a0 + 2].z = fmaf(fmaf(fs.z, wl2.z, cbase.z), p2.z, acc[a0 + 2].z);
            acc[a0 + 2].w = fmaf(fmaf(fs.w, wl2.w, cbase.w), p2.w, acc[a0 + 2].w);
            acc[a0 + 3].x = fmaf(fmaf(fs.x, wl3.x, cbase.x), p3.x, acc[a0 + 3].x);
            acc[a0 + 3].y = fmaf(fmaf(fs.y, wl3.y, cbase.y), p3.y, acc[a0 + 3].y);
            acc[a0 + 3].z = fmaf(fmaf(fs.z, wl3.z, cbase.z), p3.z, acc[a0 + 3].z);
            acc[a0 + 3].w = fmaf(fmaf(fs.w, wl3.w, cbase.w), p3.w, acc[a0 + 3].w);
        }
    }

#pragma unroll
    for (int j = 0; j < BH; j++) {
        const int b = bh * BH + j;
        atomicAdd(&out[b * NN + o + 0], acc[j].x);
        atomicAdd(&out[b * NN + o + 1], acc[j].y);
        atomicAdd(&out[b * NN + o + 2], acc[j].z);
        atomicAdd(&out[b * NN + o + 3], acc[j].w);
    }
}

extern "C" void kernel_launch(void* const* d_in, const int* in_sizes, int n_in,
                              void* d_out, int out_size) {
    const float* W         = (const float*)d_in[0];
    const float* Wlong     = (const float*)d_in[1];
    const float* Wshort    = (const float*)d_in[2];
    const float* Xd        = (const float*)d_in[3];
    const float* delaymap  = (const float*)d_in[4];
    const float* STDP_frac = (const float*)d_in[5];
    const float* signs_pre = (const float*)d_in[6];
    float* out = (float*)d_out;

    ds_zero_kernel<<<(BB * NN + 255) / 256, 256>>>(out, BB * NN);

    dim3 grid(2, (NN + EC_MAX - 1) / EC_MAX); // (2, 147) = 294 CTAs
    ds_main_kernel<<<grid, THREADS>>>(W, Wlong, Wshort, Xd, delaymap,
                                      STDP_frac, signs_pre, out);
}

// round 16
// speedup vs baseline: 1.2889x; 1.1551x over previous
#include <cuda_runtime.h>

// DeltaSynapse: I[b,o] = sum_e Weff[b,e,o] * sum_d (Xd[d,b,e]*(Wshort[d,b,e]+1)) * delaymap[d,e,o]
// Weff[b,e,o] = sg[e,o]*(W[e,o]*(1-frac[e,o]) + Wlong[b,e,o]*frac[e,o])
//
// D=8, B=16, N=2048. HBM-bound: 417 MB unique; measured practical ceiling
// ~5.65 TB/s for this 26-stream pattern (R7/R8 at the implied floor).
// R12 (full row, reg-capped): failed. R15: single-burst issue — all 26
// stream loads (w,f,dm[8],wl[16]) hoisted to the top of each e-iteration
// as one contiguous LDG burst (max outstanding sectors/warp, whole address
// set visible to the MC at once). Otherwise identical to R7 (WIN config):
// 148 CTAs (1/SM, 1 wave), 512 thr, float2/thread, 4KB runs, __ldcs,
// LDS.128 coef broadcast.

#define NN 2048
#define BB 16
#define DD 8
#define EC_MAX 28      // 74 chunks x 28 >= 2048
#define THREADS 512
#define OTILE 1024

__global__ void ds_zero_kernel(float* __restrict__ out, int n) {
    int i = blockIdx.x * blockDim.x + threadIdx.x;
    if (i < n) out[i] = 0.0f;
}

__global__ __launch_bounds__(THREADS, 1) void ds_main_kernel(
    const float* __restrict__ W,         // (N,N)
    const float* __restrict__ Wlong,     // (B,N,N)
    const float* __restrict__ Wshort,    // (D,B,N)
    const float* __restrict__ Xd,        // (D,B,N)
    const float* __restrict__ delaymap,  // (D,N,N)
    const float* __restrict__ frac,      // (N,N)
    const float* __restrict__ signs_pre, // (N,)
    float* __restrict__ out)             // (B,N)
{
    __shared__ float coef[EC_MAX][DD][BB]; // b fastest -> LDS.128 broadcast
    __shared__ float sgn_sh[EC_MAX];

    const int tid  = threadIdx.x;
    const int o    = blockIdx.x * OTILE + tid * 2;
    const int e0   = blockIdx.y * EC_MAX;
    const int eend = min(e0 + EC_MAX, NN);
    const int ecnt = eend - e0;

    // Cooperative coef preload (coalesced in e, guarded tail).
    for (int idx = tid; idx < DD * BB * EC_MAX; idx += THREADS) {
        int el   = idx % EC_MAX;
        int rest = idx / EC_MAX;
        int b    = rest % BB;
        int d    = rest / BB;
        if (el < ecnt) {
            int gi = (d * BB + b) * NN + (e0 + el);
            coef[el][d][b] = Xd[gi] * (Wshort[gi] + 1.0f);
        }
    }
    if (tid < ecnt) {
        float sp = signs_pre[e0 + tid];
        sgn_sh[tid] = (sp > 0.0f) ? 1.0f : ((sp < 0.0f) ? -1.0f : 0.0f);
    }
    __syncthreads();

    float2 acc[BB];
#pragma unroll
    for (int b = 0; b < BB; b++) acc[b] = make_float2(0.f, 0.f);

    for (int el = 0; el < ecnt; el++) {
        const int e = e0 + el;
        const long base_eo = (long)e * NN + o;

        // ---- single contiguous burst: all 26 streams issued back-to-back ----
        const float2 w2 = __ldcs((const float2*)(W + base_eo));
        const float2 f2 = __ldcs((const float2*)(frac + base_eo));

        float2 dm[DD];
#pragma unroll
        for (int d = 0; d < DD; d++)
            dm[d] = __ldcs((const float2*)(delaymap + (long)d * NN * NN + base_eo));

        float2 wl[BB];
#pragma unroll
        for (int b = 0; b < BB; b++)
            wl[b] = __ldcs((const float2*)(Wlong + (long)b * NN * NN + base_eo));
        // --------------------------------------------------------------------

        const float se = sgn_sh[el];
        const float sgx = (w2.x > 0.0f) ? se : 0.0f;
        const float sgy = (w2.y > 0.0f) ? se : 0.0f;
        float2 cbase, fs;
        cbase.x = sgx * w2.x * (1.0f - f2.x);  fs.x = sgx * f2.x;
        cbase.y = sgy * w2.y * (1.0f - f2.y);  fs.y = sgy * f2.y;

        const float4* cel = (const float4*)coef[el];

#pragma unroll
        for (int g = 0; g < BB / 4; g++) {
            float2 p0 = make_float2(0.f, 0.f), p1 = p0, p2 = p0, p3 = p0;
#pragma unroll
            for (int d = 0; d < DD; d++) {
                const float4 c = cel[d * (BB / 4) + g];   // LDS.128 broadcast
                p0.x = fmaf(dm[d].x, c.x, p0.x);  p0.y = fmaf(dm[d].y, c.x, p0.y);
                p1.x = fmaf(dm[d].x, c.y, p1.x);  p1.y = fmaf(dm[d].y, c.y, p1.y);
                p2.x = fmaf(dm[d].x, c.z, p2.x);  p2.y = fmaf(dm[d].y, c.z, p2.y);
                p3.x = fmaf(dm[d].x, c.w, p3.x);  p3.y = fmaf(dm[d].y, c.w, p3.y);
            }
            const int b0 = 4 * g;
            acc[b0 + 0].x = fmaf(fmaf(fs.x, wl[b0 + 0].x, cbase.x), p0.x, acc[b0 + 0].x);
            acc[b0 + 0].y = fmaf(fmaf(fs.y, wl[b0 + 0].y, cbase.y), p0.y, acc[b0 + 0].y);
            acc[b0 + 1].x = fmaf(fmaf(fs.x, wl[b0 + 1].x, cbase.x), p1.x, acc[b0 + 1].x);
            acc[b0 + 1].y = fmaf(fmaf(fs.y, wl[b0 + 1].y, cbase.y), p1.y, acc[b0 + 1].y);
            acc[b0 + 2].x = fmaf(fmaf(fs.x, wl[b0 + 2].x, cbase.x), p2.x, acc[b0 + 2].x);
            acc[b0 + 2].y = fmaf(fmaf(fs.y, wl[b0 + 2].y, cbase.y), p2.y, acc[b0 + 2].y);
            acc[b0 + 3].x = fmaf(fmaf(fs.x, wl[b0 + 3].x, cbase.x), p3.x, acc[b0 + 3].x);
            acc[b0 + 3].y = fmaf(fmaf(fs.y, wl[b0 + 3].y, cbase.y), p3.y, acc[b0 + 3].y);
        }
    }

#pragma unroll
    for (int b = 0; b < BB; b++) {
        atomicAdd(&out[b * NN + o + 0], acc[b].x);
        atomicAdd(&out[b * NN + o + 1], acc[b].y);
    }
}

extern "C" void kernel_launch(void* const* d_in, const int* in_sizes, int n_in,
                              void* d_out, int out_size) {
    const float* W         = (const float*)d_in[0];
    const float* Wlong     = (const float*)d_in[1];
    const float* Wshort    = (const float*)d_in[2];
    const float* Xd        = (const float*)d_in[3];
    const float* delaymap  = (const float*)d_in[4];
    const float* STDP_frac = (const float*)d_in[5];
    const float* signs_pre = (const float*)d_in[6];
    float* out = (float*)d_out;

    ds_zero_kernel<<<(BB * NN + 255) / 256, 256>>>(out, BB * NN);

    dim3 grid(NN / OTILE, (NN + EC_MAX - 1) / EC_MAX); // (2, 74) = 148 CTAs
    ds_main_kernel<<<grid, THREADS>>>(W, Wlong, Wshort, Xd, delaymap,
                                      STDP_frac, signs_pre, out);
}